// round 6
// baseline (speedup 1.0000x reference)
#include <cuda_runtime.h>
#include <cuda_bf16.h>
#include <cstdint>
#include <cstddef>

#define NN   100000
#define MAXE 1600000
#define NB   391          // ceil(NN/256)

// ---------------- device scratch ----------------
// zeroed-every-call region (single memset)
struct PreZero {
    int degi[NN];
    unsigned long long tile[NB];   // lookback state: [33:32]=state, [31:0]=sum
    unsigned int ticket;
};
__device__ PreZero g_pre;

__device__ float g_dinv[NN];
__device__ int   g_rowptr[NN + 1];
__device__ int   g_cursor[NN];
__device__ int   g_csrc[MAXE];
__device__ __nv_bfloat16 g_h1[(size_t)NN * 128];  // dinv * (x @ W1)   (bf16)
__device__ __nv_bfloat16 g_h2[(size_t)NN * 64];   // dinv * (mid @ W2) (bf16)
__device__ float g_acc[64];
__device__ unsigned int g_done;

// ---------------- inline edge dtype detection (per block) -----------------
__device__ __forceinline__ int detect_e64(const void* eidx, int* sh) {
    if (threadIdx.x < 32) {
        unsigned long long v = ((const unsigned long long*)eidx)[threadIdx.x];
        unsigned m = __ballot_sync(0xffffffffu, (v >> 32) != 0ULL);
        if (threadIdx.x == 0) *sh = (m == 0u);
    }
    __syncthreads();
    return *sh;
}

// ---------------- degree count ----------------
__global__ void k_degcount(const void* __restrict__ eidx, long long E) {
    __shared__ int sh;
    int e64 = detect_e64(eidx, &sh);
    long long i = blockIdx.x * (long long)blockDim.x + threadIdx.x;
    if (i >= E) return;
    int d;
    if (e64) d = (int)((const long long*)eidx)[E + i];
    else     d = ((const int*)eidx)[E + i];
    atomicAdd(&g_pre.degi[d], 1);
}

// ---------------- single-kernel decoupled-lookback scan (+dinv, +zero) ----
__global__ void __launch_bounds__(256) k_scanlb() {
    __shared__ int sm[256];
    __shared__ int s_bid;
    __shared__ int s_prefix;
    int tid = threadIdx.x;

    if (tid == 0) s_bid = (int)atomicAdd(&g_pre.ticket, 1u);
    __syncthreads();
    int bid = s_bid;

    int i = bid * 256 + tid;
    int v = (i < NN) ? g_pre.degi[i] : 0;
    if (i < NN) g_dinv[i] = rsqrtf((float)(v + 1));   // +1 self loop

    // inclusive scan in shared
    sm[tid] = v;
    __syncthreads();
    for (int o = 1; o < 256; o <<= 1) {
        int t = (tid >= o) ? sm[tid - o] : 0;
        __syncthreads();
        sm[tid] += t;
        __syncthreads();
    }
    int incl  = sm[tid];
    int total = sm[255];

    if (tid == 0) {
        if (bid == 0) {
            atomicExch(&g_pre.tile[0],
                       (2ULL << 32) | (unsigned long long)(unsigned)total);
            s_prefix = 0;
            // zero the output accumulator & done flag for agg2
        } else {
            atomicExch(&g_pre.tile[bid],
                       (1ULL << 32) | (unsigned long long)(unsigned)total);
            int prefix = 0;
            int j = bid - 1;
            while (true) {
                unsigned long long t;
                do { t = atomicAdd(&g_pre.tile[j], 0ULL); } while ((t >> 32) == 0ULL);
                prefix += (int)(unsigned)t;
                if ((t >> 32) == 2ULL) break;
                j--;
            }
            atomicExch(&g_pre.tile[bid],
                       (2ULL << 32) | (unsigned long long)(unsigned)(prefix + total));
            s_prefix = prefix;
        }
    }
    if (bid == 0) {
        if (tid < 64) g_acc[tid] = 0.f;
        if (tid == 64) g_done = 0u;
    }
    __syncthreads();

    int excl = s_prefix + incl - v;
    if (i < NN) { g_rowptr[i] = excl; g_cursor[i] = excl; }
    if (i == NN - 1) g_rowptr[NN] = excl + v;
}

// ---------------- scatter: csrc only ----------------
__global__ void k_scatter(const void* __restrict__ eidx, long long E) {
    __shared__ int sh;
    int e64 = detect_e64(eidx, &sh);
    long long i = blockIdx.x * (long long)blockDim.x + threadIdx.x;
    if (i >= E) return;
    int s, d;
    if (e64) {
        const long long* p = (const long long*)eidx;
        s = (int)p[i];
        d = (int)p[E + i];
    } else {
        const int* p = (const int*)eidx;
        s = p[i];
        d = p[E + i];
    }
    int pos = atomicAdd(&g_cursor[d], 1);
    g_csrc[pos] = s;
}

// ---------------- tensor-core GEMM primitives ----------------
__device__ __forceinline__ uint32_t smem_u32(const void* p) {
    return (uint32_t)__cvta_generic_to_shared(p);
}
__device__ __forceinline__ void ldsm4(uint32_t* r, uint32_t addr) {
    asm volatile("ldmatrix.sync.aligned.m8n8.x4.shared.b16 {%0,%1,%2,%3},[%4];"
                 : "=r"(r[0]), "=r"(r[1]), "=r"(r[2]), "=r"(r[3]) : "r"(addr));
}
__device__ __forceinline__ void ldsm4t(uint32_t* r, uint32_t addr) {
    asm volatile("ldmatrix.sync.aligned.m8n8.x4.trans.shared.b16 {%0,%1,%2,%3},[%4];"
                 : "=r"(r[0]), "=r"(r[1]), "=r"(r[2]), "=r"(r[3]) : "r"(addr));
}
__device__ __forceinline__ void mma16816(float* d, const uint32_t* a, const uint32_t* b) {
    asm volatile(
        "mma.sync.aligned.m16n8k16.row.col.f32.bf16.bf16.f32 "
        "{%0,%1,%2,%3},{%4,%5,%6,%7},{%8,%9},{%0,%1,%2,%3};"
        : "+f"(d[0]), "+f"(d[1]), "+f"(d[2]), "+f"(d[3])
        : "r"(a[0]), "r"(a[1]), "r"(a[2]), "r"(a[3]), "r"(b[0]), "r"(b[1]));
}

// GEMM1: C[nrows,128](bf16) = dinv[r] * (A_f32[nrows,128] @ W[128,128])
__global__ void __launch_bounds__(256)
k_gemm1(const float* __restrict__ A, const float* __restrict__ W,
        const float* __restrict__ rowscale, __nv_bfloat16* __restrict__ C,
        int nrows) {
    const int BN = 128, LDA = 136, LDB = 136;
    extern __shared__ __nv_bfloat16 smem[];
    __nv_bfloat16* As = smem;
    __nv_bfloat16* Bs = smem + 128 * LDA;

    int tid  = threadIdx.x;
    int lane = tid & 31;
    int w    = tid >> 5;
    int wm   = w & 3;
    int wn   = w >> 2;
    int row0 = blockIdx.x * 128;

    for (int idx = tid; idx < 128 * 32; idx += 256) {
        int r = idx >> 5, c4 = (idx & 31) * 4;
        float4 v = make_float4(0.f, 0.f, 0.f, 0.f);
        if (row0 + r < nrows)
            v = *(const float4*)(A + (size_t)(row0 + r) * 128 + c4);
        __nv_bfloat162 lo = __float22bfloat162_rn(make_float2(v.x, v.y));
        __nv_bfloat162 hi = __float22bfloat162_rn(make_float2(v.z, v.w));
        uint2 pk;
        pk.x = *(uint32_t*)&lo;
        pk.y = *(uint32_t*)&hi;
        *(uint2*)&As[r * LDA + c4] = pk;
    }
    for (int idx = tid; idx < 128 * 32; idx += 256) {
        int r = idx >> 5, c4 = (idx & 31) * 4;
        float4 v = *(const float4*)(W + (size_t)r * BN + c4);
        __nv_bfloat162 lo = __float22bfloat162_rn(make_float2(v.x, v.y));
        __nv_bfloat162 hi = __float22bfloat162_rn(make_float2(v.z, v.w));
        uint2 pk;
        pk.x = *(uint32_t*)&lo;
        pk.y = *(uint32_t*)&hi;
        *(uint2*)&Bs[r * LDB + c4] = pk;
    }
    __syncthreads();

    const int NF8 = 8, NT = 4;
    float acc[2][NF8][4];
#pragma unroll
    for (int i = 0; i < 2; i++)
#pragma unroll
        for (int j = 0; j < NF8; j++)
#pragma unroll
            for (int q = 0; q < 4; q++) acc[i][j][q] = 0.f;

    int rsel = lane & 15;
    int csel = (lane >> 4) * 8;
    int mw0  = wm * 32;
    int nw0  = wn * 64;

#pragma unroll
    for (int ks = 0; ks < 8; ks++) {
        int k0 = ks * 16;
        uint32_t af[2][4];
#pragma unroll
        for (int mi = 0; mi < 2; mi++)
            ldsm4(af[mi], smem_u32(&As[(mw0 + mi * 16 + rsel) * LDA + k0 + csel]));
        uint32_t bf[NT][4];
#pragma unroll
        for (int nt = 0; nt < NT; nt++)
            ldsm4t(bf[nt], smem_u32(&Bs[(k0 + rsel) * LDB + nw0 + nt * 16 + csel]));
#pragma unroll
        for (int mi = 0; mi < 2; mi++)
#pragma unroll
            for (int nj = 0; nj < NF8; nj++)
                mma16816(acc[mi][nj], af[mi], &bf[nj >> 1][(nj & 1) * 2]);
    }

    int g = lane >> 2, q = lane & 3;
#pragma unroll
    for (int mi = 0; mi < 2; mi++) {
        int r0 = row0 + mw0 + mi * 16 + g;
        float sc0 = (r0 < nrows)     ? rowscale[r0]     : 0.f;
        float sc1 = (r0 + 8 < nrows) ? rowscale[r0 + 8] : 0.f;
#pragma unroll
        for (int nj = 0; nj < NF8; nj++) {
            int col = nw0 + nj * 8 + q * 2;
            if (r0 < nrows) {
                __nv_bfloat162 v = __float22bfloat162_rn(
                    make_float2(acc[mi][nj][0] * sc0, acc[mi][nj][1] * sc0));
                *(__nv_bfloat162*)(C + (size_t)r0 * BN + col) = v;
            }
            if (r0 + 8 < nrows) {
                __nv_bfloat162 v = __float22bfloat162_rn(
                    make_float2(acc[mi][nj][2] * sc1, acc[mi][nj][3] * sc1));
                *(__nv_bfloat162*)(C + (size_t)(r0 + 8) * BN + col) = v;
            }
        }
    }
}

// ---------------- CSR gather-sum (pure adds, h pre-scaled by dinv) --------
__device__ __forceinline__ void ldrow8(const __nv_bfloat16* p, float* f) {
    uint2 u = *(const uint2*)p;
    float2 a = __bfloat1622float2(*(__nv_bfloat162*)&u.x);
    float2 b = __bfloat1622float2(*(__nv_bfloat162*)&u.y);
    f[0] = a.x; f[1] = a.y; f[2] = b.x; f[3] = b.y;
}

template <int F>
__device__ __forceinline__ void csr_gather(const __nv_bfloat16* hl, int node,
                                           float* acc) {
    ldrow8(hl + (size_t)node * F, acc);   // self row (pre-scaled)
    int beg = g_rowptr[node], end = g_rowptr[node + 1];
    int j = beg;
    for (; j + 4 <= end; j += 4) {
        int s0 = g_csrc[j],     s1 = g_csrc[j + 1];
        int s2 = g_csrc[j + 2], s3 = g_csrc[j + 3];
        float f0[4], f1[4], f2[4], f3[4];
        ldrow8(hl + (size_t)s0 * F, f0);
        ldrow8(hl + (size_t)s1 * F, f1);
        ldrow8(hl + (size_t)s2 * F, f2);
        ldrow8(hl + (size_t)s3 * F, f3);
#pragma unroll
        for (int c = 0; c < 4; c++)
            acc[c] += (f0[c] + f1[c]) + (f2[c] + f3[c]);
    }
    for (; j < end; j++) {
        int s = g_csrc[j];
        float f[4];
        ldrow8(hl + (size_t)s * F, f);
#pragma unroll
        for (int c = 0; c < 4; c++) acc[c] += f[c];
    }
}

// ---------------- fused mid layer: agg1 -> (bias,relu) -> GEMM2 -----------
// h2[node,:] = dinv[node] * ( relu(dinv[node]*gather(h1)[node,:] + b1) @ W2 )
__global__ void __launch_bounds__(256)
k_mid(const __nv_bfloat16* __restrict__ h1, const float* __restrict__ b1,
      const float* __restrict__ W2, __nv_bfloat16* __restrict__ h2, int nrows) {
    const int BN = 64, LDA = 136, LDB = 72;
    extern __shared__ __nv_bfloat16 smem[];
    __nv_bfloat16* As = smem;                  // [128][136]
    __nv_bfloat16* Bs = smem + 128 * LDA;      // [128][72]

    int tid  = threadIdx.x;
    int lane = tid & 31;
    int w    = tid >> 5;
    int row0 = blockIdx.x * 128;

    // Bs = bf16(W2)
    for (int idx = tid; idx < 128 * 16; idx += 256) {
        int r = idx >> 4, c4 = (idx & 15) * 4;
        float4 v = *(const float4*)(W2 + (size_t)r * BN + c4);
        __nv_bfloat162 lo = __float22bfloat162_rn(make_float2(v.x, v.y));
        __nv_bfloat162 hi = __float22bfloat162_rn(make_float2(v.z, v.w));
        uint2 pk;
        pk.x = *(uint32_t*)&lo;
        pk.y = *(uint32_t*)&hi;
        *(uint2*)&Bs[r * LDB + c4] = pk;
    }

    // gather phase: warp w handles rows w, w+8, ..., w+120
    {
        float4 bb = *(const float4*)(b1 + lane * 4);
        const __nv_bfloat16* hl = h1 + lane * 4;
        for (int r = w; r < 128; r += 8) {
            int node = row0 + r;
            uint2 pk = make_uint2(0u, 0u);
            if (node < nrows) {
                float acc[4];
                csr_gather<128>(hl, node, acc);
                float dn = g_dinv[node];
                float2 lo = make_float2(fmaxf(dn * acc[0] + bb.x, 0.f),
                                        fmaxf(dn * acc[1] + bb.y, 0.f));
                float2 hi = make_float2(fmaxf(dn * acc[2] + bb.z, 0.f),
                                        fmaxf(dn * acc[3] + bb.w, 0.f));
                __nv_bfloat162 l2 = __float22bfloat162_rn(lo);
                __nv_bfloat162 h2v = __float22bfloat162_rn(hi);
                pk.x = *(uint32_t*)&l2;
                pk.y = *(uint32_t*)&h2v;
            }
            *(uint2*)&As[r * LDA + lane * 4] = pk;
        }
    }
    __syncthreads();

    // MMA phase
    const int NF8 = 4, NT = 2;
    int wm = w & 3;
    int wn = w >> 2;
    float acc[2][NF8][4];
#pragma unroll
    for (int i = 0; i < 2; i++)
#pragma unroll
        for (int j = 0; j < NF8; j++)
#pragma unroll
            for (int q = 0; q < 4; q++) acc[i][j][q] = 0.f;

    int rsel = lane & 15;
    int csel = (lane >> 4) * 8;
    int mw0  = wm * 32;
    int nw0  = wn * 32;

#pragma unroll
    for (int ks = 0; ks < 8; ks++) {
        int k0 = ks * 16;
        uint32_t af[2][4];
#pragma unroll
        for (int mi = 0; mi < 2; mi++)
            ldsm4(af[mi], smem_u32(&As[(mw0 + mi * 16 + rsel) * LDA + k0 + csel]));
        uint32_t bf[NT][4];
#pragma unroll
        for (int nt = 0; nt < NT; nt++)
            ldsm4t(bf[nt], smem_u32(&Bs[(k0 + rsel) * LDB + nw0 + nt * 16 + csel]));
#pragma unroll
        for (int mi = 0; mi < 2; mi++)
#pragma unroll
            for (int nj = 0; nj < NF8; nj++)
                mma16816(acc[mi][nj], af[mi], &bf[nj >> 1][(nj & 1) * 2]);
    }

    int g = lane >> 2, q = lane & 3;
#pragma unroll
    for (int mi = 0; mi < 2; mi++) {
        int r0 = row0 + mw0 + mi * 16 + g;
        float sc0 = (r0 < nrows)     ? g_dinv[r0]     : 0.f;
        float sc1 = (r0 + 8 < nrows) ? g_dinv[r0 + 8] : 0.f;
#pragma unroll
        for (int nj = 0; nj < NF8; nj++) {
            int col = nw0 + nj * 8 + q * 2;
            if (r0 < nrows) {
                __nv_bfloat162 v = __float22bfloat162_rn(
                    make_float2(acc[mi][nj][0] * sc0, acc[mi][nj][1] * sc0));
                *(__nv_bfloat162*)(h2 + (size_t)r0 * BN + col) = v;
            }
            if (r0 + 8 < nrows) {
                __nv_bfloat162 v = __float22bfloat162_rn(
                    make_float2(acc[mi][nj][2] * sc1, acc[mi][nj][3] * sc1));
                *(__nv_bfloat162*)(h2 + (size_t)(r0 + 8) * BN + col) = v;
            }
        }
    }
}

// agg layer 2 (2 nodes per warp) fused with sigmoid + mean + final output
__global__ void __launch_bounds__(256)
k_agg2(const __nv_bfloat16* __restrict__ h, const float* __restrict__ b2,
       float* __restrict__ out) {
    __shared__ float sm[64];
    if (threadIdx.x < 64) sm[threadIdx.x] = 0.f;
    __syncthreads();

    int lane = threadIdx.x & 31;
    int half = lane >> 4;
    int l16  = lane & 15;
    int wg   = (blockIdx.x * 256 + threadIdx.x) >> 5;
    int stride = gridDim.x * 8 * 2;

    float4 bb = *(const float4*)(b2 + l16 * 4);
    float s[4] = {0.f, 0.f, 0.f, 0.f};

    for (int node = wg * 2 + half; node < NN; node += stride) {
        float acc[4];
        csr_gather<64>(h + l16 * 4, node, acc);
        float dn = g_dinv[node];
        s[0] += 1.0f / (1.0f + __expf(-(dn * acc[0] + bb.x)));
        s[1] += 1.0f / (1.0f + __expf(-(dn * acc[1] + bb.y)));
        s[2] += 1.0f / (1.0f + __expf(-(dn * acc[2] + bb.z)));
        s[3] += 1.0f / (1.0f + __expf(-(dn * acc[3] + bb.w)));
    }
#pragma unroll
    for (int c = 0; c < 4; c++) atomicAdd(&sm[l16 * 4 + c], s[c]);
    __syncthreads();
    if (threadIdx.x < 64) atomicAdd(&g_acc[threadIdx.x], sm[threadIdx.x]);
    __threadfence();
    __syncthreads();

    __shared__ unsigned s_last;
    if (threadIdx.x == 0)
        s_last = (atomicAdd(&g_done, 1u) == (unsigned)(gridDim.x - 1));
    __syncthreads();
    if (s_last) {
        __threadfence();
        if (threadIdx.x < 64) {
            float v = atomicAdd(&g_acc[threadIdx.x], 0.f);
            out[threadIdx.x] = v * (1.0f / NN);
        }
    }
}

// ---------------- launch ----------------
extern "C" void kernel_launch(void* const* d_in, const int* in_sizes, int n_in,
                              void* d_out, int out_size) {
    const float* x  = (const float*)d_in[0];
    const void*  ei = d_in[1];
    const float* W1 = (const float*)d_in[2];
    const float* b1 = (const float*)d_in[3];
    const float* W2 = (const float*)d_in[4];
    const float* b2 = (const float*)d_in[5];
    float* out = (float*)d_out;
    long long E = in_sizes[1] / 2;

    __nv_bfloat16 *h1, *h2;
    float *dinv;
    void *prez;
    cudaGetSymbolAddress((void**)&h1, g_h1);
    cudaGetSymbolAddress((void**)&h2, g_h2);
    cudaGetSymbolAddress((void**)&dinv, g_dinv);
    cudaGetSymbolAddress(&prez, g_pre);

    const int SM1   = (128 * 136 + 128 * 136) * 2;  // 69632 B
    const int SMMID = (128 * 136 + 128 * 72) * 2;   // 53248 B

    static cudaStream_t s2 = nullptr;
    static cudaEvent_t ev0 = nullptr, ev1 = nullptr;
    if (!s2) {
        cudaFuncSetAttribute(k_gemm1,
                             cudaFuncAttributeMaxDynamicSharedMemorySize, SM1);
        cudaFuncSetAttribute(k_mid,
                             cudaFuncAttributeMaxDynamicSharedMemorySize, SMMID);
        cudaStreamCreateWithFlags(&s2, cudaStreamNonBlocking);
        cudaEventCreateWithFlags(&ev0, cudaEventDisableTiming);
        cudaEventCreateWithFlags(&ev1, cudaEventDisableTiming);
    }

    int eb = (int)((E + 255) / 256);
    int gb = (NN + 127) / 128;

    // preprocessing chain (main stream)
    cudaMemsetAsync(prez, 0, sizeof(PreZero), 0);
    k_degcount<<<eb, 256>>>(ei, E);
    k_scanlb<<<NB, 256>>>();

    // fork: GEMM1 on side stream (needs dinv from scanlb)
    cudaEventRecord(ev1, 0);
    cudaStreamWaitEvent(s2, ev1, 0);
    k_gemm1<<<gb, 256, SM1, s2>>>(x, W1, dinv, h1, NN);
    cudaEventRecord(ev0, s2);

    k_scatter<<<eb, 256>>>(ei, E);

    // join: k_mid needs CSR (main) + h1 (s2)
    cudaStreamWaitEvent(0, ev0, 0);
    k_mid<<<gb, 256, SMMID>>>(h1, b1, W2, h2, NN);
    k_agg2<<<1024, 256>>>(h2, b2, out);
}

// round 7
// speedup vs baseline: 1.0613x; 1.0613x over previous
#include <cuda_runtime.h>
#include <cuda_bf16.h>
#include <cstdint>
#include <cstddef>

#define NN   100000
#define MAXE 1600000
#define NB   391          // ceil(NN/256)

// ---------------- device scratch ----------------
// zeroed-every-call region (single memset)
struct PreZero {
    int degi[NN];
    unsigned long long tile[NB];   // lookback state: [33:32]=state, [31:0]=sum
    unsigned int ticket;
};
__device__ PreZero g_pre;

__device__ float g_dinv[NN];
__device__ int   g_rowptr[NN + 1];
__device__ int   g_epos[MAXE];     // within-bucket rank of each edge
__device__ int   g_csrc[MAXE];
__device__ __nv_bfloat16 g_h1[(size_t)NN * 128];  // dinv * (x @ W1)     (bf16)
__device__ __nv_bfloat16 g_t1[(size_t)NN * 128];  // relu(agg1 + b1)     (bf16)
__device__ __nv_bfloat16 g_h2[(size_t)NN * 64];   // dinv * (t1 @ W2)    (bf16)
__device__ float g_acc[64];
__device__ unsigned int g_done;

// ---------------- inline edge dtype detection (per block) -----------------
__device__ __forceinline__ int detect_e64(const void* eidx, int* sh) {
    if (threadIdx.x < 32) {
        unsigned long long v = ((const unsigned long long*)eidx)[threadIdx.x];
        unsigned m = __ballot_sync(0xffffffffu, (v >> 32) != 0ULL);
        if (threadIdx.x == 0) *sh = (m == 0u);
    }
    __syncthreads();
    return *sh;
}

// ---------------- degree count (also records per-edge bucket rank) --------
__global__ void k_degcount(const void* __restrict__ eidx, long long E) {
    __shared__ int sh;
    int e64 = detect_e64(eidx, &sh);
    long long i = blockIdx.x * (long long)blockDim.x + threadIdx.x;
    if (i >= E) return;
    int d;
    if (e64) d = (int)((const long long*)eidx)[E + i];
    else     d = ((const int*)eidx)[E + i];
    g_epos[i] = atomicAdd(&g_pre.degi[d], 1);
}

// ---------------- single-kernel decoupled-lookback scan (+dinv, +zero) ----
__global__ void __launch_bounds__(256) k_scanlb() {
    __shared__ int sm[256];
    __shared__ int s_bid;
    __shared__ int s_prefix;
    int tid = threadIdx.x;

    if (tid == 0) s_bid = (int)atomicAdd(&g_pre.ticket, 1u);
    __syncthreads();
    int bid = s_bid;

    int i = bid * 256 + tid;
    int v = (i < NN) ? g_pre.degi[i] : 0;
    if (i < NN) g_dinv[i] = rsqrtf((float)(v + 1));   // +1 self loop

    sm[tid] = v;
    __syncthreads();
    for (int o = 1; o < 256; o <<= 1) {
        int t = (tid >= o) ? sm[tid - o] : 0;
        __syncthreads();
        sm[tid] += t;
        __syncthreads();
    }
    int incl  = sm[tid];
    int total = sm[255];

    if (tid == 0) {
        if (bid == 0) {
            atomicExch(&g_pre.tile[0],
                       (2ULL << 32) | (unsigned long long)(unsigned)total);
            s_prefix = 0;
        } else {
            atomicExch(&g_pre.tile[bid],
                       (1ULL << 32) | (unsigned long long)(unsigned)total);
            int prefix = 0;
            int j = bid - 1;
            while (true) {
                unsigned long long t;
                do { t = atomicAdd(&g_pre.tile[j], 0ULL); } while ((t >> 32) == 0ULL);
                prefix += (int)(unsigned)t;
                if ((t >> 32) == 2ULL) break;
                j--;
            }
            atomicExch(&g_pre.tile[bid],
                       (2ULL << 32) | (unsigned long long)(unsigned)(prefix + total));
            s_prefix = prefix;
        }
    }
    if (bid == 0) {
        if (tid < 64) g_acc[tid] = 0.f;
        if (tid == 64) g_done = 0u;
    }
    __syncthreads();

    int excl = s_prefix + incl - v;
    if (i < NN) g_rowptr[i] = excl;
    if (i == NN - 1) g_rowptr[NN] = excl + v;
}

// ---------------- scatter: atomic-free (rowptr[d] + epos[i]) --------------
__global__ void k_scatter(const void* __restrict__ eidx, long long E) {
    __shared__ int sh;
    int e64 = detect_e64(eidx, &sh);
    long long i = blockIdx.x * (long long)blockDim.x + threadIdx.x;
    if (i >= E) return;
    int s, d;
    if (e64) {
        const long long* p = (const long long*)eidx;
        s = (int)p[i];
        d = (int)p[E + i];
    } else {
        const int* p = (const int*)eidx;
        s = p[i];
        d = p[E + i];
    }
    g_csrc[g_rowptr[d] + g_epos[i]] = s;
}

// ---------------- tensor-core GEMM primitives ----------------
__device__ __forceinline__ uint32_t smem_u32(const void* p) {
    return (uint32_t)__cvta_generic_to_shared(p);
}
__device__ __forceinline__ void ldsm4(uint32_t* r, uint32_t addr) {
    asm volatile("ldmatrix.sync.aligned.m8n8.x4.shared.b16 {%0,%1,%2,%3},[%4];"
                 : "=r"(r[0]), "=r"(r[1]), "=r"(r[2]), "=r"(r[3]) : "r"(addr));
}
__device__ __forceinline__ void ldsm4t(uint32_t* r, uint32_t addr) {
    asm volatile("ldmatrix.sync.aligned.m8n8.x4.trans.shared.b16 {%0,%1,%2,%3},[%4];"
                 : "=r"(r[0]), "=r"(r[1]), "=r"(r[2]), "=r"(r[3]) : "r"(addr));
}
__device__ __forceinline__ void mma16816(float* d, const uint32_t* a, const uint32_t* b) {
    asm volatile(
        "mma.sync.aligned.m16n8k16.row.col.f32.bf16.bf16.f32 "
        "{%0,%1,%2,%3},{%4,%5,%6,%7},{%8,%9},{%0,%1,%2,%3};"
        : "+f"(d[0]), "+f"(d[1]), "+f"(d[2]), "+f"(d[3])
        : "r"(a[0]), "r"(a[1]), "r"(a[2]), "r"(a[3]), "r"(b[0]), "r"(b[1]));
}

// C[nrows,BN](bf16) = rowscale[r] * (A[nrows,128] @ W[128,BN]).
template <int BN, bool A_BF16>
__global__ void __launch_bounds__(256)
k_gemm_tc(const void* __restrict__ Av, const float* __restrict__ W,
          const float* __restrict__ rowscale, __nv_bfloat16* __restrict__ C,
          int nrows) {
    const int LDA = 136;
    const int LDB = BN + 8;
    extern __shared__ __nv_bfloat16 smem[];
    __nv_bfloat16* As = smem;
    __nv_bfloat16* Bs = smem + 128 * LDA;

    int tid  = threadIdx.x;
    int lane = tid & 31;
    int w    = tid >> 5;
    int wm   = w & 3;
    int wn   = w >> 2;
    int row0 = blockIdx.x * 128;

    if (A_BF16) {
        const __nv_bfloat16* A = (const __nv_bfloat16*)Av;
        for (int idx = tid; idx < 128 * 16; idx += 256) {
            int r = idx >> 4, c8 = (idx & 15) * 8;
            uint4 v = make_uint4(0, 0, 0, 0);
            if (row0 + r < nrows)
                v = *(const uint4*)(A + (size_t)(row0 + r) * 128 + c8);
            *(uint4*)&As[r * LDA + c8] = v;
        }
    } else {
        const float* A = (const float*)Av;
        for (int idx = tid; idx < 128 * 32; idx += 256) {
            int r = idx >> 5, c4 = (idx & 31) * 4;
            float4 v = make_float4(0.f, 0.f, 0.f, 0.f);
            if (row0 + r < nrows)
                v = *(const float4*)(A + (size_t)(row0 + r) * 128 + c4);
            __nv_bfloat162 lo = __float22bfloat162_rn(make_float2(v.x, v.y));
            __nv_bfloat162 hi = __float22bfloat162_rn(make_float2(v.z, v.w));
            uint2 pk;
            pk.x = *(uint32_t*)&lo;
            pk.y = *(uint32_t*)&hi;
            *(uint2*)&As[r * LDA + c4] = pk;
        }
    }
    for (int idx = tid; idx < 128 * (BN / 4); idx += 256) {
        int r = idx / (BN / 4), c4 = (idx % (BN / 4)) * 4;
        float4 v = *(const float4*)(W + (size_t)r * BN + c4);
        __nv_bfloat162 lo = __float22bfloat162_rn(make_float2(v.x, v.y));
        __nv_bfloat162 hi = __float22bfloat162_rn(make_float2(v.z, v.w));
        uint2 pk;
        pk.x = *(uint32_t*)&lo;
        pk.y = *(uint32_t*)&hi;
        *(uint2*)&Bs[r * LDB + c4] = pk;
    }
    __syncthreads();

    const int NF8 = BN / 16;
    const int NT  = NF8 / 2;
    float acc[2][NF8][4];
#pragma unroll
    for (int i = 0; i < 2; i++)
#pragma unroll
        for (int j = 0; j < NF8; j++)
#pragma unroll
            for (int q = 0; q < 4; q++) acc[i][j][q] = 0.f;

    int rsel = lane & 15;
    int csel = (lane >> 4) * 8;
    int mw0  = wm * 32;
    int nw0  = wn * (BN / 2);

#pragma unroll
    for (int ks = 0; ks < 8; ks++) {
        int k0 = ks * 16;
        uint32_t af[2][4];
#pragma unroll
        for (int mi = 0; mi < 2; mi++)
            ldsm4(af[mi], smem_u32(&As[(mw0 + mi * 16 + rsel) * LDA + k0 + csel]));
        uint32_t bf[NT][4];
#pragma unroll
        for (int nt = 0; nt < NT; nt++)
            ldsm4t(bf[nt], smem_u32(&Bs[(k0 + rsel) * LDB + nw0 + nt * 16 + csel]));
#pragma unroll
        for (int mi = 0; mi < 2; mi++)
#pragma unroll
            for (int nj = 0; nj < NF8; nj++)
                mma16816(acc[mi][nj], af[mi], &bf[nj >> 1][(nj & 1) * 2]);
    }

    int g = lane >> 2, q = lane & 3;
#pragma unroll
    for (int mi = 0; mi < 2; mi++) {
        int r0 = row0 + mw0 + mi * 16 + g;
        float sc0 = (r0 < nrows)     ? rowscale[r0]     : 0.f;
        float sc1 = (r0 + 8 < nrows) ? rowscale[r0 + 8] : 0.f;
#pragma unroll
        for (int nj = 0; nj < NF8; nj++) {
            int col = nw0 + nj * 8 + q * 2;
            if (r0 < nrows) {
                __nv_bfloat162 v = __float22bfloat162_rn(
                    make_float2(acc[mi][nj][0] * sc0, acc[mi][nj][1] * sc0));
                *(__nv_bfloat162*)(C + (size_t)r0 * BN + col) = v;
            }
            if (r0 + 8 < nrows) {
                __nv_bfloat162 v = __float22bfloat162_rn(
                    make_float2(acc[mi][nj][2] * sc1, acc[mi][nj][3] * sc1));
                *(__nv_bfloat162*)(C + (size_t)(r0 + 8) * BN + col) = v;
            }
        }
    }
}

// ---------------- CSR gather-sum (pure adds, h pre-scaled by dinv) --------
__device__ __forceinline__ void ldrow8(const __nv_bfloat16* p, float* f) {
    uint2 u = *(const uint2*)p;
    float2 a = __bfloat1622float2(*(__nv_bfloat162*)&u.x);
    float2 b = __bfloat1622float2(*(__nv_bfloat162*)&u.y);
    f[0] = a.x; f[1] = a.y; f[2] = b.x; f[3] = b.y;
}

template <int F>
__device__ __forceinline__ void csr_gather(const __nv_bfloat16* hl, int node,
                                           float* acc) {
    ldrow8(hl + (size_t)node * F, acc);   // self row (pre-scaled)
    int beg = g_rowptr[node], end = g_rowptr[node + 1];
    int j = beg;
    for (; j + 4 <= end; j += 4) {
        int s0 = g_csrc[j],     s1 = g_csrc[j + 1];
        int s2 = g_csrc[j + 2], s3 = g_csrc[j + 3];
        float f0[4], f1[4], f2[4], f3[4];
        ldrow8(hl + (size_t)s0 * F, f0);
        ldrow8(hl + (size_t)s1 * F, f1);
        ldrow8(hl + (size_t)s2 * F, f2);
        ldrow8(hl + (size_t)s3 * F, f3);
#pragma unroll
        for (int c = 0; c < 4; c++)
            acc[c] += (f0[c] + f1[c]) + (f2[c] + f3[c]);
    }
    for (; j < end; j++) {
        int s = g_csrc[j];
        float f[4];
        ldrow8(hl + (size_t)s * F, f);
#pragma unroll
        for (int c = 0; c < 4; c++) acc[c] += f[c];
    }
}

// agg layer 1: t1[node,:] = bf16(relu(dinv[node]*gathersum + b1))
__global__ void __launch_bounds__(256)
k_agg1(const __nv_bfloat16* __restrict__ h, const float* __restrict__ b1,
       __nv_bfloat16* __restrict__ t1) {
    int node = (blockIdx.x * 256 + threadIdx.x) >> 5;
    int lane = threadIdx.x & 31;
    if (node >= NN) return;
    float acc[4];
    csr_gather<128>(h + lane * 4, node, acc);
    float dn = g_dinv[node];
    float4 bb = *(const float4*)(b1 + lane * 4);
    float2 lo = make_float2(fmaxf(dn * acc[0] + bb.x, 0.f),
                            fmaxf(dn * acc[1] + bb.y, 0.f));
    float2 hi = make_float2(fmaxf(dn * acc[2] + bb.z, 0.f),
                            fmaxf(dn * acc[3] + bb.w, 0.f));
    uint2 pk;
    __nv_bfloat162 l2 = __float22bfloat162_rn(lo);
    __nv_bfloat162 h2 = __float22bfloat162_rn(hi);
    pk.x = *(uint32_t*)&l2;
    pk.y = *(uint32_t*)&h2;
    *(uint2*)(t1 + (size_t)node * 128 + lane * 4) = pk;
}

// agg layer 2 (2 nodes per warp) fused with sigmoid + mean + final output
__global__ void __launch_bounds__(256)
k_agg2(const __nv_bfloat16* __restrict__ h, const float* __restrict__ b2,
       float* __restrict__ out) {
    __shared__ float sm[64];
    if (threadIdx.x < 64) sm[threadIdx.x] = 0.f;
    __syncthreads();

    int lane = threadIdx.x & 31;
    int half = lane >> 4;
    int l16  = lane & 15;
    int wg   = (blockIdx.x * 256 + threadIdx.x) >> 5;
    int stride = gridDim.x * 8 * 2;

    float4 bb = *(const float4*)(b2 + l16 * 4);
    float s[4] = {0.f, 0.f, 0.f, 0.f};

    for (int node = wg * 2 + half; node < NN; node += stride) {
        float acc[4];
        csr_gather<64>(h + l16 * 4, node, acc);
        float dn = g_dinv[node];
        s[0] += 1.0f / (1.0f + __expf(-(dn * acc[0] + bb.x)));
        s[1] += 1.0f / (1.0f + __expf(-(dn * acc[1] + bb.y)));
        s[2] += 1.0f / (1.0f + __expf(-(dn * acc[2] + bb.z)));
        s[3] += 1.0f / (1.0f + __expf(-(dn * acc[3] + bb.w)));
    }
#pragma unroll
    for (int c = 0; c < 4; c++) atomicAdd(&sm[l16 * 4 + c], s[c]);
    __syncthreads();
    if (threadIdx.x < 64) atomicAdd(&g_acc[threadIdx.x], sm[threadIdx.x]);
    __threadfence();
    __syncthreads();

    __shared__ unsigned s_last;
    if (threadIdx.x == 0)
        s_last = (atomicAdd(&g_done, 1u) == (unsigned)(gridDim.x - 1));
    __syncthreads();
    if (s_last) {
        __threadfence();
        if (threadIdx.x < 64) {
            float v = atomicAdd(&g_acc[threadIdx.x], 0.f);
            out[threadIdx.x] = v * (1.0f / NN);
        }
    }
}

// ---------------- launch ----------------
extern "C" void kernel_launch(void* const* d_in, const int* in_sizes, int n_in,
                              void* d_out, int out_size) {
    const float* x  = (const float*)d_in[0];
    const void*  ei = d_in[1];
    const float* W1 = (const float*)d_in[2];
    const float* b1 = (const float*)d_in[3];
    const float* W2 = (const float*)d_in[4];
    const float* b2 = (const float*)d_in[5];
    float* out = (float*)d_out;
    long long E = in_sizes[1] / 2;

    __nv_bfloat16 *h1, *t1, *h2;
    float *dinv;
    void *prez;
    cudaGetSymbolAddress((void**)&h1, g_h1);
    cudaGetSymbolAddress((void**)&t1, g_t1);
    cudaGetSymbolAddress((void**)&h2, g_h2);
    cudaGetSymbolAddress((void**)&dinv, g_dinv);
    cudaGetSymbolAddress(&prez, g_pre);

    const int SM1 = (128 * 136 + 128 * 136) * 2;  // 69632 B
    const int SM2 = (128 * 136 + 128 * 72) * 2;   // 53248 B

    static cudaStream_t s2 = nullptr;
    static cudaEvent_t ev0 = nullptr, ev1 = nullptr;
    if (!s2) {
        cudaFuncSetAttribute(k_gemm_tc<128, false>,
                             cudaFuncAttributeMaxDynamicSharedMemorySize, SM1);
        cudaFuncSetAttribute(k_gemm_tc<64, true>,
                             cudaFuncAttributeMaxDynamicSharedMemorySize, SM2);
        cudaStreamCreateWithFlags(&s2, cudaStreamNonBlocking);
        cudaEventCreateWithFlags(&ev0, cudaEventDisableTiming);
        cudaEventCreateWithFlags(&ev1, cudaEventDisableTiming);
    }

    int eb = (int)((E + 255) / 256);
    int gb = (NN + 127) / 128;
    int wb = (NN * 32 + 255) / 256;

    // preprocessing chain (main stream)
    cudaMemsetAsync(prez, 0, sizeof(PreZero), 0);
    k_degcount<<<eb, 256>>>(ei, E);
    k_scanlb<<<NB, 256>>>();

    // fork: GEMM1 on side stream (needs dinv from scanlb)
    cudaEventRecord(ev1, 0);
    cudaStreamWaitEvent(s2, ev1, 0);
    k_gemm_tc<128, false><<<gb, 256, SM1, s2>>>(x, W1, dinv, h1, NN);
    cudaEventRecord(ev0, s2);

    k_scatter<<<eb, 256>>>(ei, E);

    // join: agg1 needs CSR (main) + h1 (s2)
    cudaStreamWaitEvent(0, ev0, 0);
    k_agg1<<<wb, 256>>>(h1, b1, t1);

    // Layer 2
    k_gemm_tc<64, true><<<gb, 256, SM2>>>(t1, W2, dinv, h2, NN);
    k_agg2<<<1024, 256>>>(h2, b2, out);
}

// round 8
// speedup vs baseline: 1.1101x; 1.0460x over previous
#include <cuda_runtime.h>
#include <cuda_bf16.h>
#include <cstdint>
#include <cstddef>

#define NN   100000
#define MAXE 1600000
#define NB   391          // ceil(NN/256)

// ---------------- device scratch ----------------
__device__ int   g_degi[NN];       // zeroed each call (single memset)
__device__ float g_dinv[NN];
__device__ int   g_rowptr[NN + 1];
__device__ int   g_bsum[NB];
__device__ int   g_boff[NB];
__device__ int   g_epos[MAXE];     // within-bucket rank of each edge
__device__ int   g_csrc[MAXE];
__device__ __nv_bfloat16 g_h1[(size_t)NN * 128];  // dinv * (x @ W1)     (bf16)
__device__ __nv_bfloat16 g_t1[(size_t)NN * 128];  // relu(agg1 + b1)     (bf16)
__device__ __nv_bfloat16 g_h2[(size_t)NN * 64];   // dinv * (t1 @ W2)    (bf16)
__device__ float g_acc[64];
__device__ unsigned int g_done;

// ---------------- inline edge dtype detection (per block) -----------------
__device__ __forceinline__ int detect_e64(const void* eidx, int* sh) {
    if (threadIdx.x < 32) {
        unsigned long long v = ((const unsigned long long*)eidx)[threadIdx.x];
        unsigned m = __ballot_sync(0xffffffffu, (v >> 32) != 0ULL);
        if (threadIdx.x == 0) *sh = (m == 0u);
    }
    __syncthreads();
    return *sh;
}

// ---------------- degree count (also records per-edge bucket rank) --------
__global__ void k_degcount(const void* __restrict__ eidx, long long E) {
    __shared__ int sh;
    int e64 = detect_e64(eidx, &sh);
    long long i = blockIdx.x * (long long)blockDim.x + threadIdx.x;
    if (i >= E) return;
    int d;
    if (e64) d = (int)((const long long*)eidx)[E + i];
    else     d = ((const int*)eidx)[E + i];
    g_epos[i] = atomicAdd(&g_degi[d], 1);
}

// ---------------- scan stage 1 (+ dinv) ----------------
__global__ void k_scan1() {
    __shared__ int sm[256];
    int i = blockIdx.x * 256 + threadIdx.x;
    int v = (i < NN) ? g_degi[i] : 0;
    if (i < NN) g_dinv[i] = rsqrtf((float)(v + 1));   // +1 self loop
    sm[threadIdx.x] = v;
    __syncthreads();
    for (int o = 128; o > 0; o >>= 1) {
        if (threadIdx.x < o) sm[threadIdx.x] += sm[threadIdx.x + o];
        __syncthreads();
    }
    if (threadIdx.x == 0) g_bsum[blockIdx.x] = sm[0];
}

// ---------------- scan stage 2 (+ zero acc/done) ----------------
__global__ void k_scan2() {
    __shared__ int sm[512];
    int v = (threadIdx.x < NB) ? g_bsum[threadIdx.x] : 0;
    sm[threadIdx.x] = v;
    __syncthreads();
    for (int o = 1; o < 512; o <<= 1) {
        int t = (threadIdx.x >= o) ? sm[threadIdx.x - o] : 0;
        __syncthreads();
        sm[threadIdx.x] += t;
        __syncthreads();
    }
    if (threadIdx.x < NB) g_boff[threadIdx.x] = sm[threadIdx.x] - v;  // exclusive
    if (threadIdx.x < 64) g_acc[threadIdx.x] = 0.f;
    if (threadIdx.x == 64) g_done = 0u;
}

// ---------------- scan stage 3 ----------------
__global__ void k_scan3() {
    __shared__ int sm[256];
    int i = blockIdx.x * 256 + threadIdx.x;
    int v = (i < NN) ? g_degi[i] : 0;
    sm[threadIdx.x] = v;
    __syncthreads();
    for (int o = 1; o < 256; o <<= 1) {
        int t = (threadIdx.x >= o) ? sm[threadIdx.x - o] : 0;
        __syncthreads();
        sm[threadIdx.x] += t;
        __syncthreads();
    }
    int excl = sm[threadIdx.x] - v + g_boff[blockIdx.x];
    if (i < NN) g_rowptr[i] = excl;
    if (i == NN - 1) g_rowptr[NN] = excl + v;
}

// ---------------- scatter: atomic-free (rowptr[d] + epos[i]) --------------
__global__ void k_scatter(const void* __restrict__ eidx, long long E) {
    __shared__ int sh;
    int e64 = detect_e64(eidx, &sh);
    long long i = blockIdx.x * (long long)blockDim.x + threadIdx.x;
    if (i >= E) return;
    int s, d;
    if (e64) {
        const long long* p = (const long long*)eidx;
        s = (int)p[i];
        d = (int)p[E + i];
    } else {
        const int* p = (const int*)eidx;
        s = p[i];
        d = p[E + i];
    }
    g_csrc[g_rowptr[d] + g_epos[i]] = s;
}

// ---------------- tensor-core GEMM primitives ----------------
__device__ __forceinline__ uint32_t smem_u32(const void* p) {
    return (uint32_t)__cvta_generic_to_shared(p);
}
__device__ __forceinline__ void ldsm4(uint32_t* r, uint32_t addr) {
    asm volatile("ldmatrix.sync.aligned.m8n8.x4.shared.b16 {%0,%1,%2,%3},[%4];"
                 : "=r"(r[0]), "=r"(r[1]), "=r"(r[2]), "=r"(r[3]) : "r"(addr));
}
__device__ __forceinline__ void ldsm4t(uint32_t* r, uint32_t addr) {
    asm volatile("ldmatrix.sync.aligned.m8n8.x4.trans.shared.b16 {%0,%1,%2,%3},[%4];"
                 : "=r"(r[0]), "=r"(r[1]), "=r"(r[2]), "=r"(r[3]) : "r"(addr));
}
__device__ __forceinline__ void mma16816(float* d, const uint32_t* a, const uint32_t* b) {
    asm volatile(
        "mma.sync.aligned.m16n8k16.row.col.f32.bf16.bf16.f32 "
        "{%0,%1,%2,%3},{%4,%5,%6,%7},{%8,%9},{%0,%1,%2,%3};"
        : "+f"(d[0]), "+f"(d[1]), "+f"(d[2]), "+f"(d[3])
        : "r"(a[0]), "r"(a[1]), "r"(a[2]), "r"(a[3]), "r"(b[0]), "r"(b[1]));
}

// C[nrows,BN](bf16) = rowscale[r] * (A[nrows,128] @ W[128,BN]).
template <int BN, bool A_BF16>
__global__ void __launch_bounds__(256)
k_gemm_tc(const void* __restrict__ Av, const float* __restrict__ W,
          const float* __restrict__ rowscale, __nv_bfloat16* __restrict__ C,
          int nrows) {
    const int LDA = 136;
    const int LDB = BN + 8;
    extern __shared__ __nv_bfloat16 smem[];
    __nv_bfloat16* As = smem;
    __nv_bfloat16* Bs = smem + 128 * LDA;

    int tid  = threadIdx.x;
    int lane = tid & 31;
    int w    = tid >> 5;
    int wm   = w & 3;
    int wn   = w >> 2;
    int row0 = blockIdx.x * 128;

    if (A_BF16) {
        const __nv_bfloat16* A = (const __nv_bfloat16*)Av;
        for (int idx = tid; idx < 128 * 16; idx += 256) {
            int r = idx >> 4, c8 = (idx & 15) * 8;
            uint4 v = make_uint4(0, 0, 0, 0);
            if (row0 + r < nrows)
                v = *(const uint4*)(A + (size_t)(row0 + r) * 128 + c8);
            *(uint4*)&As[r * LDA + c8] = v;
        }
    } else {
        const float* A = (const float*)Av;
        for (int idx = tid; idx < 128 * 32; idx += 256) {
            int r = idx >> 5, c4 = (idx & 31) * 4;
            float4 v = make_float4(0.f, 0.f, 0.f, 0.f);
            if (row0 + r < nrows)
                v = *(const float4*)(A + (size_t)(row0 + r) * 128 + c4);
            __nv_bfloat162 lo = __float22bfloat162_rn(make_float2(v.x, v.y));
            __nv_bfloat162 hi = __float22bfloat162_rn(make_float2(v.z, v.w));
            uint2 pk;
            pk.x = *(uint32_t*)&lo;
            pk.y = *(uint32_t*)&hi;
            *(uint2*)&As[r * LDA + c4] = pk;
        }
    }
    for (int idx = tid; idx < 128 * (BN / 4); idx += 256) {
        int r = idx / (BN / 4), c4 = (idx % (BN / 4)) * 4;
        float4 v = *(const float4*)(W + (size_t)r * BN + c4);
        __nv_bfloat162 lo = __float22bfloat162_rn(make_float2(v.x, v.y));
        __nv_bfloat162 hi = __float22bfloat162_rn(make_float2(v.z, v.w));
        uint2 pk;
        pk.x = *(uint32_t*)&lo;
        pk.y = *(uint32_t*)&hi;
        *(uint2*)&Bs[r * LDB + c4] = pk;
    }
    __syncthreads();

    const int NF8 = BN / 16;
    const int NT  = NF8 / 2;
    float acc[2][NF8][4];
#pragma unroll
    for (int i = 0; i < 2; i++)
#pragma unroll
        for (int j = 0; j < NF8; j++)
#pragma unroll
            for (int q = 0; q < 4; q++) acc[i][j][q] = 0.f;

    int rsel = lane & 15;
    int csel = (lane >> 4) * 8;
    int mw0  = wm * 32;
    int nw0  = wn * (BN / 2);

#pragma unroll
    for (int ks = 0; ks < 8; ks++) {
        int k0 = ks * 16;
        uint32_t af[2][4];
#pragma unroll
        for (int mi = 0; mi < 2; mi++)
            ldsm4(af[mi], smem_u32(&As[(mw0 + mi * 16 + rsel) * LDA + k0 + csel]));
        uint32_t bf[NT][4];
#pragma unroll
        for (int nt = 0; nt < NT; nt++)
            ldsm4t(bf[nt], smem_u32(&Bs[(k0 + rsel) * LDB + nw0 + nt * 16 + csel]));
#pragma unroll
        for (int mi = 0; mi < 2; mi++)
#pragma unroll
            for (int nj = 0; nj < NF8; nj++)
                mma16816(acc[mi][nj], af[mi], &bf[nj >> 1][(nj & 1) * 2]);
    }

    int g = lane >> 2, q = lane & 3;
#pragma unroll
    for (int mi = 0; mi < 2; mi++) {
        int r0 = row0 + mw0 + mi * 16 + g;
        float sc0 = (r0 < nrows)     ? rowscale[r0]     : 0.f;
        float sc1 = (r0 + 8 < nrows) ? rowscale[r0 + 8] : 0.f;
#pragma unroll
        for (int nj = 0; nj < NF8; nj++) {
            int col = nw0 + nj * 8 + q * 2;
            if (r0 < nrows) {
                __nv_bfloat162 v = __float22bfloat162_rn(
                    make_float2(acc[mi][nj][0] * sc0, acc[mi][nj][1] * sc0));
                *(__nv_bfloat162*)(C + (size_t)r0 * BN + col) = v;
            }
            if (r0 + 8 < nrows) {
                __nv_bfloat162 v = __float22bfloat162_rn(
                    make_float2(acc[mi][nj][2] * sc1, acc[mi][nj][3] * sc1));
                *(__nv_bfloat162*)(C + (size_t)(r0 + 8) * BN + col) = v;
            }
        }
    }
}

// ---------------- CSR gather-sum (pure adds, h pre-scaled by dinv) --------
__device__ __forceinline__ void ldrow8(const __nv_bfloat16* p, float* f) {
    uint2 u = *(const uint2*)p;
    float2 a = __bfloat1622float2(*(__nv_bfloat162*)&u.x);
    float2 b = __bfloat1622float2(*(__nv_bfloat162*)&u.y);
    f[0] = a.x; f[1] = a.y; f[2] = b.x; f[3] = b.y;
}

template <int F>
__device__ __forceinline__ void csr_gather(const __nv_bfloat16* hl, int node,
                                           float* acc) {
    ldrow8(hl + (size_t)node * F, acc);   // self row (pre-scaled)
    int beg = g_rowptr[node], end = g_rowptr[node + 1];
    int j = beg;
    for (; j + 4 <= end; j += 4) {
        int s0 = g_csrc[j],     s1 = g_csrc[j + 1];
        int s2 = g_csrc[j + 2], s3 = g_csrc[j + 3];
        float f0[4], f1[4], f2[4], f3[4];
        ldrow8(hl + (size_t)s0 * F, f0);
        ldrow8(hl + (size_t)s1 * F, f1);
        ldrow8(hl + (size_t)s2 * F, f2);
        ldrow8(hl + (size_t)s3 * F, f3);
#pragma unroll
        for (int c = 0; c < 4; c++)
            acc[c] += (f0[c] + f1[c]) + (f2[c] + f3[c]);
    }
    for (; j < end; j++) {
        int s = g_csrc[j];
        float f[4];
        ldrow8(hl + (size_t)s * F, f);
#pragma unroll
        for (int c = 0; c < 4; c++) acc[c] += f[c];
    }
}

// agg layer 1: t1[node,:] = bf16(relu(dinv[node]*gathersum + b1))
__global__ void __launch_bounds__(256)
k_agg1(const __nv_bfloat16* __restrict__ h, const float* __restrict__ b1,
       __nv_bfloat16* __restrict__ t1) {
    int node = (blockIdx.x * 256 + threadIdx.x) >> 5;
    int lane = threadIdx.x & 31;
    if (node >= NN) return;
    float acc[4];
    csr_gather<128>(h + lane * 4, node, acc);
    float dn = g_dinv[node];
    float4 bb = *(const float4*)(b1 + lane * 4);
    float2 lo = make_float2(fmaxf(dn * acc[0] + bb.x, 0.f),
                            fmaxf(dn * acc[1] + bb.y, 0.f));
    float2 hi = make_float2(fmaxf(dn * acc[2] + bb.z, 0.f),
                            fmaxf(dn * acc[3] + bb.w, 0.f));
    uint2 pk;
    __nv_bfloat162 l2 = __float22bfloat162_rn(lo);
    __nv_bfloat162 h2 = __float22bfloat162_rn(hi);
    pk.x = *(uint32_t*)&l2;
    pk.y = *(uint32_t*)&h2;
    *(uint2*)(t1 + (size_t)node * 128 + lane * 4) = pk;
}

// agg layer 2 (2 nodes per warp) fused with sigmoid + mean + final output
__global__ void __launch_bounds__(256)
k_agg2(const __nv_bfloat16* __restrict__ h, const float* __restrict__ b2,
       float* __restrict__ out) {
    __shared__ float sm[64];
    if (threadIdx.x < 64) sm[threadIdx.x] = 0.f;
    __syncthreads();

    int lane = threadIdx.x & 31;
    int half = lane >> 4;
    int l16  = lane & 15;
    int wg   = (blockIdx.x * 256 + threadIdx.x) >> 5;
    int stride = gridDim.x * 8 * 2;

    float4 bb = *(const float4*)(b2 + l16 * 4);
    float s[4] = {0.f, 0.f, 0.f, 0.f};

    for (int node = wg * 2 + half; node < NN; node += stride) {
        float acc[4];
        csr_gather<64>(h + l16 * 4, node, acc);
        float dn = g_dinv[node];
        s[0] += 1.0f / (1.0f + __expf(-(dn * acc[0] + bb.x)));
        s[1] += 1.0f / (1.0f + __expf(-(dn * acc[1] + bb.y)));
        s[2] += 1.0f / (1.0f + __expf(-(dn * acc[2] + bb.z)));
        s[3] += 1.0f / (1.0f + __expf(-(dn * acc[3] + bb.w)));
    }
#pragma unroll
    for (int c = 0; c < 4; c++) atomicAdd(&sm[l16 * 4 + c], s[c]);
    __syncthreads();
    if (threadIdx.x < 64) atomicAdd(&g_acc[threadIdx.x], sm[threadIdx.x]);
    __threadfence();
    __syncthreads();

    __shared__ unsigned s_last;
    if (threadIdx.x == 0)
        s_last = (atomicAdd(&g_done, 1u) == (unsigned)(gridDim.x - 1));
    __syncthreads();
    if (s_last) {
        __threadfence();
        if (threadIdx.x < 64) {
            float v = atomicAdd(&g_acc[threadIdx.x], 0.f);
            out[threadIdx.x] = v * (1.0f / NN);
        }
    }
}

// ---------------- launch ----------------
extern "C" void kernel_launch(void* const* d_in, const int* in_sizes, int n_in,
                              void* d_out, int out_size) {
    const float* x  = (const float*)d_in[0];
    const void*  ei = d_in[1];
    const float* W1 = (const float*)d_in[2];
    const float* b1 = (const float*)d_in[3];
    const float* W2 = (const float*)d_in[4];
    const float* b2 = (const float*)d_in[5];
    float* out = (float*)d_out;
    long long E = in_sizes[1] / 2;

    __nv_bfloat16 *h1, *t1, *h2;
    float *dinv;
    int *degi;
    cudaGetSymbolAddress((void**)&h1, g_h1);
    cudaGetSymbolAddress((void**)&t1, g_t1);
    cudaGetSymbolAddress((void**)&h2, g_h2);
    cudaGetSymbolAddress((void**)&dinv, g_dinv);
    cudaGetSymbolAddress((void**)&degi, g_degi);

    const int SM1 = (128 * 136 + 128 * 136) * 2;  // 69632 B
    const int SM2 = (128 * 136 + 128 * 72) * 2;   // 53248 B

    static cudaStream_t s2 = nullptr;
    static cudaEvent_t ev0 = nullptr, ev1 = nullptr;
    if (!s2) {
        cudaFuncSetAttribute(k_gemm_tc<128, false>,
                             cudaFuncAttributeMaxDynamicSharedMemorySize, SM1);
        cudaFuncSetAttribute(k_gemm_tc<64, true>,
                             cudaFuncAttributeMaxDynamicSharedMemorySize, SM2);
        cudaStreamCreateWithFlags(&s2, cudaStreamNonBlocking);
        cudaEventCreateWithFlags(&ev0, cudaEventDisableTiming);
        cudaEventCreateWithFlags(&ev1, cudaEventDisableTiming);
    }

    int eb = (int)((E + 255) / 256);
    int gb = (NN + 127) / 128;
    int wb = (NN * 32 + 255) / 256;

    // preprocessing chain (main stream)
    cudaMemsetAsync(degi, 0, NN * sizeof(int), 0);
    k_degcount<<<eb, 256>>>(ei, E);
    k_scan1<<<NB, 256>>>();

    // fork: GEMM1 on side stream (needs dinv from scan1)
    cudaEventRecord(ev1, 0);
    cudaStreamWaitEvent(s2, ev1, 0);
    k_gemm_tc<128, false><<<gb, 256, SM1, s2>>>(x, W1, dinv, h1, NN);
    cudaEventRecord(ev0, s2);

    k_scan2<<<1, 512>>>();
    k_scan3<<<NB, 256>>>();
    k_scatter<<<eb, 256>>>(ei, E);

    // join: agg1 needs CSR (main) + h1 (s2)
    cudaStreamWaitEvent(0, ev0, 0);
    k_agg1<<<wb, 256>>>(h1, b1, t1);

    // Layer 2
    k_gemm_tc<64, true><<<gb, 256, SM2>>>(t1, W2, dinv, h2, NN);
    k_agg2<<<1024, 256>>>(h2, b2, out);
}

// round 9
// speedup vs baseline: 1.1235x; 1.0121x over previous
#include <cuda_runtime.h>
#include <cuda_bf16.h>
#include <cuda_fp16.h>
#include <cstdint>
#include <cstddef>

#define NN   100000
#define MAXE 1600000
#define NB   391          // ceil(NN/256)

// ---------------- device scratch ----------------
__device__ int   g_degi[NN];       // zeroed each call (single memset)
__device__ float g_dinv[NN];
__device__ int   g_rowptr[NN + 1];
__device__ int   g_bsum[NB];
__device__ int   g_boff[NB];
__device__ int   g_epos[MAXE];     // within-bucket rank of each edge
__device__ int   g_csrc[MAXE];
__device__ uint8_t       g_h1[(size_t)NN * 128];  // fp8: 16*dinv*(x@W1)
__device__ __nv_bfloat16 g_t1[(size_t)NN * 128];  // relu(agg1 + b1)     (bf16)
__device__ __nv_bfloat16 g_h2[(size_t)NN * 64];   // dinv * (t1 @ W2)    (bf16)
__device__ float g_acc[64];
__device__ unsigned int g_done;

// ---------------- inline edge dtype detection (per block) -----------------
__device__ __forceinline__ int detect_e64(const void* eidx, int* sh) {
    if (threadIdx.x < 32) {
        unsigned long long v = ((const unsigned long long*)eidx)[threadIdx.x];
        unsigned m = __ballot_sync(0xffffffffu, (v >> 32) != 0ULL);
        if (threadIdx.x == 0) *sh = (m == 0u);
    }
    __syncthreads();
    return *sh;
}

// ---------------- degree count (4 edges/thread, records bucket rank) ------
__global__ void k_degcount(const void* __restrict__ eidx, long long E) {
    __shared__ int sh;
    int e64 = detect_e64(eidx, &sh);
    long long base = (blockIdx.x * (long long)blockDim.x + threadIdx.x) * 4;
    if (base >= E) return;
    bool fast = (base + 3 < E) && ((E & 3LL) == 0);
    if (e64) {
        const long long* p = (const long long*)eidx + E;   // dst half
        if (fast) {
            longlong4 d4 = *(const longlong4*)(p + base);
            int4 r;
            r.x = atomicAdd(&g_degi[(int)d4.x], 1);
            r.y = atomicAdd(&g_degi[(int)d4.y], 1);
            r.z = atomicAdd(&g_degi[(int)d4.z], 1);
            r.w = atomicAdd(&g_degi[(int)d4.w], 1);
            *(int4*)&g_epos[base] = r;
        } else {
            for (int k = 0; k < 4 && base + k < E; k++)
                g_epos[base + k] = atomicAdd(&g_degi[(int)p[base + k]], 1);
        }
    } else {
        const int* p = (const int*)eidx + E;
        if (fast) {
            int4 d4 = *(const int4*)(p + base);
            int4 r;
            r.x = atomicAdd(&g_degi[d4.x], 1);
            r.y = atomicAdd(&g_degi[d4.y], 1);
            r.z = atomicAdd(&g_degi[d4.z], 1);
            r.w = atomicAdd(&g_degi[d4.w], 1);
            *(int4*)&g_epos[base] = r;
        } else {
            for (int k = 0; k < 4 && base + k < E; k++)
                g_epos[base + k] = atomicAdd(&g_degi[p[base + k]], 1);
        }
    }
}

// ---------------- scan stage 1 (+ dinv) ----------------
__global__ void k_scan1() {
    __shared__ int sm[256];
    int i = blockIdx.x * 256 + threadIdx.x;
    int v = (i < NN) ? g_degi[i] : 0;
    if (i < NN) g_dinv[i] = rsqrtf((float)(v + 1));   // +1 self loop
    sm[threadIdx.x] = v;
    __syncthreads();
    for (int o = 128; o > 0; o >>= 1) {
        if (threadIdx.x < o) sm[threadIdx.x] += sm[threadIdx.x + o];
        __syncthreads();
    }
    if (threadIdx.x == 0) g_bsum[blockIdx.x] = sm[0];
}

// ---------------- scan stage 2 (+ zero acc/done) ----------------
__global__ void k_scan2() {
    __shared__ int sm[512];
    int v = (threadIdx.x < NB) ? g_bsum[threadIdx.x] : 0;
    sm[threadIdx.x] = v;
    __syncthreads();
    for (int o = 1; o < 512; o <<= 1) {
        int t = (threadIdx.x >= o) ? sm[threadIdx.x - o] : 0;
        __syncthreads();
        sm[threadIdx.x] += t;
        __syncthreads();
    }
    if (threadIdx.x < NB) g_boff[threadIdx.x] = sm[threadIdx.x] - v;  // exclusive
    if (threadIdx.x < 64) g_acc[threadIdx.x] = 0.f;
    if (threadIdx.x == 64) g_done = 0u;
}

// ---------------- scan stage 3 ----------------
__global__ void k_scan3() {
    __shared__ int sm[256];
    int i = blockIdx.x * 256 + threadIdx.x;
    int v = (i < NN) ? g_degi[i] : 0;
    sm[threadIdx.x] = v;
    __syncthreads();
    for (int o = 1; o < 256; o <<= 1) {
        int t = (threadIdx.x >= o) ? sm[threadIdx.x - o] : 0;
        __syncthreads();
        sm[threadIdx.x] += t;
        __syncthreads();
    }
    int excl = sm[threadIdx.x] - v + g_boff[blockIdx.x];
    if (i < NN) g_rowptr[i] = excl;
    if (i == NN - 1) g_rowptr[NN] = excl + v;
}

// ---------------- scatter: atomic-free, 4 edges/thread --------------------
__global__ void k_scatter(const void* __restrict__ eidx, long long E) {
    __shared__ int sh;
    int e64 = detect_e64(eidx, &sh);
    long long base = (blockIdx.x * (long long)blockDim.x + threadIdx.x) * 4;
    if (base >= E) return;
    bool fast = (base + 3 < E) && ((E & 3LL) == 0);
    if (e64) {
        const long long* ps = (const long long*)eidx;
        const long long* pd = ps + E;
        if (fast) {
            longlong4 s4 = *(const longlong4*)(ps + base);
            longlong4 d4 = *(const longlong4*)(pd + base);
            int4 ep = *(const int4*)&g_epos[base];
            g_csrc[g_rowptr[(int)d4.x] + ep.x] = (int)s4.x;
            g_csrc[g_rowptr[(int)d4.y] + ep.y] = (int)s4.y;
            g_csrc[g_rowptr[(int)d4.z] + ep.z] = (int)s4.z;
            g_csrc[g_rowptr[(int)d4.w] + ep.w] = (int)s4.w;
        } else {
            for (int k = 0; k < 4 && base + k < E; k++)
                g_csrc[g_rowptr[(int)pd[base + k]] + g_epos[base + k]] =
                    (int)ps[base + k];
        }
    } else {
        const int* ps = (const int*)eidx;
        const int* pd = ps + E;
        if (fast) {
            int4 s4 = *(const int4*)(ps + base);
            int4 d4 = *(const int4*)(pd + base);
            int4 ep = *(const int4*)&g_epos[base];
            g_csrc[g_rowptr[d4.x] + ep.x] = s4.x;
            g_csrc[g_rowptr[d4.y] + ep.y] = s4.y;
            g_csrc[g_rowptr[d4.z] + ep.z] = s4.z;
            g_csrc[g_rowptr[d4.w] + ep.w] = s4.w;
        } else {
            for (int k = 0; k < 4 && base + k < E; k++)
                g_csrc[g_rowptr[pd[base + k]] + g_epos[base + k]] = ps[base + k];
        }
    }
}

// ---------------- fp8 helpers ----------------
__device__ __forceinline__ uint16_t pack_e4m3_2(float lo, float hi) {
    uint16_t r;
    asm("cvt.rn.satfinite.e4m3x2.f32 %0, %1, %2;" : "=h"(r) : "f"(hi), "f"(lo));
    return r;
}
__device__ __forceinline__ void unpack_e4m3_4(uint32_t v, float* f) {
    uint32_t h01, h23;
    asm("cvt.rn.f16x2.e4m3x2 %0, %1;" : "=r"(h01)
        : "h"((unsigned short)(v & 0xffffu)));
    asm("cvt.rn.f16x2.e4m3x2 %0, %1;" : "=r"(h23)
        : "h"((unsigned short)(v >> 16)));
    float2 fa = __half22float2(*reinterpret_cast<__half2*>(&h01));
    float2 fb = __half22float2(*reinterpret_cast<__half2*>(&h23));
    f[0] = fa.x; f[1] = fa.y; f[2] = fb.x; f[3] = fb.y;
}

// ---------------- tensor-core GEMM primitives ----------------
__device__ __forceinline__ uint32_t smem_u32(const void* p) {
    return (uint32_t)__cvta_generic_to_shared(p);
}
__device__ __forceinline__ void ldsm4(uint32_t* r, uint32_t addr) {
    asm volatile("ldmatrix.sync.aligned.m8n8.x4.shared.b16 {%0,%1,%2,%3},[%4];"
                 : "=r"(r[0]), "=r"(r[1]), "=r"(r[2]), "=r"(r[3]) : "r"(addr));
}
__device__ __forceinline__ void ldsm4t(uint32_t* r, uint32_t addr) {
    asm volatile("ldmatrix.sync.aligned.m8n8.x4.trans.shared.b16 {%0,%1,%2,%3},[%4];"
                 : "=r"(r[0]), "=r"(r[1]), "=r"(r[2]), "=r"(r[3]) : "r"(addr));
}
__device__ __forceinline__ void mma16816(float* d, const uint32_t* a, const uint32_t* b) {
    asm volatile(
        "mma.sync.aligned.m16n8k16.row.col.f32.bf16.bf16.f32 "
        "{%0,%1,%2,%3},{%4,%5,%6,%7},{%8,%9},{%0,%1,%2,%3};"
        : "+f"(d[0]), "+f"(d[1]), "+f"(d[2]), "+f"(d[3])
        : "r"(a[0]), "r"(a[1]), "r"(a[2]), "r"(a[3]), "r"(b[0]), "r"(b[1]));
}

// C[nrows,BN] = rowscale[r] * (A[nrows,128] @ W[128,BN]).
// OUT_FP8: C is fp8 e4m3 with extra x16 scale; else C is bf16.
template <int BN, bool A_BF16, bool OUT_FP8>
__global__ void __launch_bounds__(256)
k_gemm_tc(const void* __restrict__ Av, const float* __restrict__ W,
          const float* __restrict__ rowscale, void* __restrict__ Cv,
          int nrows) {
    const int LDA = 136;
    const int LDB = BN + 8;
    extern __shared__ __nv_bfloat16 smem[];
    __nv_bfloat16* As = smem;
    __nv_bfloat16* Bs = smem + 128 * LDA;

    int tid  = threadIdx.x;
    int lane = tid & 31;
    int w    = tid >> 5;
    int wm   = w & 3;
    int wn   = w >> 2;
    int row0 = blockIdx.x * 128;

    if (A_BF16) {
        const __nv_bfloat16* A = (const __nv_bfloat16*)Av;
        for (int idx = tid; idx < 128 * 16; idx += 256) {
            int r = idx >> 4, c8 = (idx & 15) * 8;
            uint4 v = make_uint4(0, 0, 0, 0);
            if (row0 + r < nrows)
                v = *(const uint4*)(A + (size_t)(row0 + r) * 128 + c8);
            *(uint4*)&As[r * LDA + c8] = v;
        }
    } else {
        const float* A = (const float*)Av;
        for (int idx = tid; idx < 128 * 32; idx += 256) {
            int r = idx >> 5, c4 = (idx & 31) * 4;
            float4 v = make_float4(0.f, 0.f, 0.f, 0.f);
            if (row0 + r < nrows)
                v = *(const float4*)(A + (size_t)(row0 + r) * 128 + c4);
            __nv_bfloat162 lo = __float22bfloat162_rn(make_float2(v.x, v.y));
            __nv_bfloat162 hi = __float22bfloat162_rn(make_float2(v.z, v.w));
            uint2 pk;
            pk.x = *(uint32_t*)&lo;
            pk.y = *(uint32_t*)&hi;
            *(uint2*)&As[r * LDA + c4] = pk;
        }
    }
    for (int idx = tid; idx < 128 * (BN / 4); idx += 256) {
        int r = idx / (BN / 4), c4 = (idx % (BN / 4)) * 4;
        float4 v = *(const float4*)(W + (size_t)r * BN + c4);
        __nv_bfloat162 lo = __float22bfloat162_rn(make_float2(v.x, v.y));
        __nv_bfloat162 hi = __float22bfloat162_rn(make_float2(v.z, v.w));
        uint2 pk;
        pk.x = *(uint32_t*)&lo;
        pk.y = *(uint32_t*)&hi;
        *(uint2*)&Bs[r * LDB + c4] = pk;
    }
    __syncthreads();

    const int NF8 = BN / 16;
    const int NT  = NF8 / 2;
    float acc[2][NF8][4];
#pragma unroll
    for (int i = 0; i < 2; i++)
#pragma unroll
        for (int j = 0; j < NF8; j++)
#pragma unroll
            for (int q = 0; q < 4; q++) acc[i][j][q] = 0.f;

    int rsel = lane & 15;
    int csel = (lane >> 4) * 8;
    int mw0  = wm * 32;
    int nw0  = wn * (BN / 2);

#pragma unroll
    for (int ks = 0; ks < 8; ks++) {
        int k0 = ks * 16;
        uint32_t af[2][4];
#pragma unroll
        for (int mi = 0; mi < 2; mi++)
            ldsm4(af[mi], smem_u32(&As[(mw0 + mi * 16 + rsel) * LDA + k0 + csel]));
        uint32_t bf[NT][4];
#pragma unroll
        for (int nt = 0; nt < NT; nt++)
            ldsm4t(bf[nt], smem_u32(&Bs[(k0 + rsel) * LDB + nw0 + nt * 16 + csel]));
#pragma unroll
        for (int mi = 0; mi < 2; mi++)
#pragma unroll
            for (int nj = 0; nj < NF8; nj++)
                mma16816(acc[mi][nj], af[mi], &bf[nj >> 1][(nj & 1) * 2]);
    }

    int g = lane >> 2, q = lane & 3;
#pragma unroll
    for (int mi = 0; mi < 2; mi++) {
        int r0 = row0 + mw0 + mi * 16 + g;
        float sc0 = (r0 < nrows)     ? rowscale[r0]     : 0.f;
        float sc1 = (r0 + 8 < nrows) ? rowscale[r0 + 8] : 0.f;
        if (OUT_FP8) { sc0 *= 16.f; sc1 *= 16.f; }
#pragma unroll
        for (int nj = 0; nj < NF8; nj++) {
            int col = nw0 + nj * 8 + q * 2;
            if (OUT_FP8) {
                uint8_t* C = (uint8_t*)Cv;
                if (r0 < nrows)
                    *(uint16_t*)(C + (size_t)r0 * BN + col) =
                        pack_e4m3_2(acc[mi][nj][0] * sc0, acc[mi][nj][1] * sc0);
                if (r0 + 8 < nrows)
                    *(uint16_t*)(C + (size_t)(r0 + 8) * BN + col) =
                        pack_e4m3_2(acc[mi][nj][2] * sc1, acc[mi][nj][3] * sc1);
            } else {
                __nv_bfloat16* C = (__nv_bfloat16*)Cv;
                if (r0 < nrows) {
                    __nv_bfloat162 v = __float22bfloat162_rn(
                        make_float2(acc[mi][nj][0] * sc0, acc[mi][nj][1] * sc0));
                    *(__nv_bfloat162*)(C + (size_t)r0 * BN + col) = v;
                }
                if (r0 + 8 < nrows) {
                    __nv_bfloat162 v = __float22bfloat162_rn(
                        make_float2(acc[mi][nj][2] * sc1, acc[mi][nj][3] * sc1));
                    *(__nv_bfloat162*)(C + (size_t)(r0 + 8) * BN + col) = v;
                }
            }
        }
    }
}

// ---------------- CSR gather-sum (pure adds, h pre-scaled by dinv) --------
__device__ __forceinline__ void ldrow8(const __nv_bfloat16* p, float* f) {
    uint2 u = *(const uint2*)p;
    float2 a = __bfloat1622float2(*(__nv_bfloat162*)&u.x);
    float2 b = __bfloat1622float2(*(__nv_bfloat162*)&u.y);
    f[0] = a.x; f[1] = a.y; f[2] = b.x; f[3] = b.y;
}

// bf16 variant (F = row length in elements)
template <int F>
__device__ __forceinline__ void csr_gather(const __nv_bfloat16* hl, int node,
                                           float* acc) {
    ldrow8(hl + (size_t)node * F, acc);   // self row (pre-scaled)
    int beg = g_rowptr[node], end = g_rowptr[node + 1];
    int j = beg;
    for (; j + 4 <= end; j += 4) {
        int s0 = g_csrc[j],     s1 = g_csrc[j + 1];
        int s2 = g_csrc[j + 2], s3 = g_csrc[j + 3];
        float f0[4], f1[4], f2[4], f3[4];
        ldrow8(hl + (size_t)s0 * F, f0);
        ldrow8(hl + (size_t)s1 * F, f1);
        ldrow8(hl + (size_t)s2 * F, f2);
        ldrow8(hl + (size_t)s3 * F, f3);
#pragma unroll
        for (int c = 0; c < 4; c++)
            acc[c] += (f0[c] + f1[c]) + (f2[c] + f3[c]);
    }
    for (; j < end; j++) {
        int s = g_csrc[j];
        float f[4];
        ldrow8(hl + (size_t)s * F, f);
#pragma unroll
        for (int c = 0; c < 4; c++) acc[c] += f[c];
    }
}

// fp8 variant: row length 128 bytes, lane offset in bytes
__device__ __forceinline__ void csr_gather_fp8(const uint8_t* hl, int node,
                                               float* acc) {
    unpack_e4m3_4(*(const uint32_t*)(hl + (size_t)node * 128), acc);
    int beg = g_rowptr[node], end = g_rowptr[node + 1];
    int j = beg;
    for (; j + 4 <= end; j += 4) {
        int s0 = g_csrc[j],     s1 = g_csrc[j + 1];
        int s2 = g_csrc[j + 2], s3 = g_csrc[j + 3];
        uint32_t v0 = *(const uint32_t*)(hl + (size_t)s0 * 128);
        uint32_t v1 = *(const uint32_t*)(hl + (size_t)s1 * 128);
        uint32_t v2 = *(const uint32_t*)(hl + (size_t)s2 * 128);
        uint32_t v3 = *(const uint32_t*)(hl + (size_t)s3 * 128);
        float f0[4], f1[4], f2[4], f3[4];
        unpack_e4m3_4(v0, f0);
        unpack_e4m3_4(v1, f1);
        unpack_e4m3_4(v2, f2);
        unpack_e4m3_4(v3, f3);
#pragma unroll
        for (int c = 0; c < 4; c++)
            acc[c] += (f0[c] + f1[c]) + (f2[c] + f3[c]);
    }
    for (; j < end; j++) {
        int s = g_csrc[j];
        float f[4];
        unpack_e4m3_4(*(const uint32_t*)(hl + (size_t)s * 128), f);
#pragma unroll
        for (int c = 0; c < 4; c++) acc[c] += f[c];
    }
}

// agg layer 1 (fp8 input): t1 = bf16(relu(dinv/16 * gathersum + b1))
__global__ void __launch_bounds__(256)
k_agg1(const uint8_t* __restrict__ h, const float* __restrict__ b1,
       __nv_bfloat16* __restrict__ t1) {
    int node = (blockIdx.x * 256 + threadIdx.x) >> 5;
    int lane = threadIdx.x & 31;
    if (node >= NN) return;
    float acc[4];
    csr_gather_fp8(h + lane * 4, node, acc);
    float dn = g_dinv[node] * 0.0625f;   // undo the x16 fp8 scale
    float4 bb = *(const float4*)(b1 + lane * 4);
    float2 lo = make_float2(fmaxf(dn * acc[0] + bb.x, 0.f),
                            fmaxf(dn * acc[1] + bb.y, 0.f));
    float2 hi = make_float2(fmaxf(dn * acc[2] + bb.z, 0.f),
                            fmaxf(dn * acc[3] + bb.w, 0.f));
    uint2 pk;
    __nv_bfloat162 l2 = __float22bfloat162_rn(lo);
    __nv_bfloat162 h2 = __float22bfloat162_rn(hi);
    pk.x = *(uint32_t*)&l2;
    pk.y = *(uint32_t*)&h2;
    *(uint2*)(t1 + (size_t)node * 128 + lane * 4) = pk;
}

// agg layer 2 (2 nodes per warp) fused with sigmoid + mean + final output
__global__ void __launch_bounds__(256)
k_agg2(const __nv_bfloat16* __restrict__ h, const float* __restrict__ b2,
       float* __restrict__ out) {
    __shared__ float sm[64];
    if (threadIdx.x < 64) sm[threadIdx.x] = 0.f;
    __syncthreads();

    int lane = threadIdx.x & 31;
    int half = lane >> 4;
    int l16  = lane & 15;
    int wg   = (blockIdx.x * 256 + threadIdx.x) >> 5;
    int stride = gridDim.x * 8 * 2;

    float4 bb = *(const float4*)(b2 + l16 * 4);
    float s[4] = {0.f, 0.f, 0.f, 0.f};

    for (int node = wg * 2 + half; node < NN; node += stride) {
        float acc[4];
        csr_gather<64>(h + l16 * 4, node, acc);
        float dn = g_dinv[node];
        s[0] += 1.0f / (1.0f + __expf(-(dn * acc[0] + bb.x)));
        s[1] += 1.0f / (1.0f + __expf(-(dn * acc[1] + bb.y)));
        s[2] += 1.0f / (1.0f + __expf(-(dn * acc[2] + bb.z)));
        s[3] += 1.0f / (1.0f + __expf(-(dn * acc[3] + bb.w)));
    }
#pragma unroll
    for (int c = 0; c < 4; c++) atomicAdd(&sm[l16 * 4 + c], s[c]);
    __syncthreads();
    if (threadIdx.x < 64) atomicAdd(&g_acc[threadIdx.x], sm[threadIdx.x]);
    __threadfence();
    __syncthreads();

    __shared__ unsigned s_last;
    if (threadIdx.x == 0)
        s_last = (atomicAdd(&g_done, 1u) == (unsigned)(gridDim.x - 1));
    __syncthreads();
    if (s_last) {
        __threadfence();
        if (threadIdx.x < 64) {
            float v = atomicAdd(&g_acc[threadIdx.x], 0.f);
            out[threadIdx.x] = v * (1.0f / NN);
        }
    }
}

// ---------------- launch ----------------
extern "C" void kernel_launch(void* const* d_in, const int* in_sizes, int n_in,
                              void* d_out, int out_size) {
    const float* x  = (const float*)d_in[0];
    const void*  ei = d_in[1];
    const float* W1 = (const float*)d_in[2];
    const float* b1 = (const float*)d_in[3];
    const float* W2 = (const float*)d_in[4];
    const float* b2 = (const float*)d_in[5];
    float* out = (float*)d_out;
    long long E = in_sizes[1] / 2;

    uint8_t *h1;
    __nv_bfloat16 *t1, *h2;
    float *dinv;
    int *degi;
    cudaGetSymbolAddress((void**)&h1, g_h1);
    cudaGetSymbolAddress((void**)&t1, g_t1);
    cudaGetSymbolAddress((void**)&h2, g_h2);
    cudaGetSymbolAddress((void**)&dinv, g_dinv);
    cudaGetSymbolAddress((void**)&degi, g_degi);

    const int SM1 = (128 * 136 + 128 * 136) * 2;  // 69632 B
    const int SM2 = (128 * 136 + 128 * 72) * 2;   // 53248 B

    static cudaStream_t s2 = nullptr;
    static cudaEvent_t ev0 = nullptr, ev1 = nullptr;
    if (!s2) {
        cudaFuncSetAttribute(k_gemm_tc<128, false, true>,
                             cudaFuncAttributeMaxDynamicSharedMemorySize, SM1);
        cudaFuncSetAttribute(k_gemm_tc<64, true, false>,
                             cudaFuncAttributeMaxDynamicSharedMemorySize, SM2);
        cudaStreamCreateWithFlags(&s2, cudaStreamNonBlocking);
        cudaEventCreateWithFlags(&ev0, cudaEventDisableTiming);
        cudaEventCreateWithFlags(&ev1, cudaEventDisableTiming);
    }

    int eb4 = (int)((E + 1023) / 1024);   // 4 edges per thread
    int gb = (NN + 127) / 128;
    int wb = (NN * 32 + 255) / 256;

    // preprocessing chain (main stream)
    cudaMemsetAsync(degi, 0, NN * sizeof(int), 0);
    k_degcount<<<eb4, 256>>>(ei, E);
    k_scan1<<<NB, 256>>>();

    // fork: GEMM1 on side stream (needs dinv from scan1)
    cudaEventRecord(ev1, 0);
    cudaStreamWaitEvent(s2, ev1, 0);
    k_gemm_tc<128, false, true><<<gb, 256, SM1, s2>>>(x, W1, dinv, h1, NN);
    cudaEventRecord(ev0, s2);

    k_scan2<<<1, 512>>>();
    k_scan3<<<NB, 256>>>();
    k_scatter<<<eb4, 256>>>(ei, E);

    // join: agg1 needs CSR (main) + h1 (s2)
    cudaStreamWaitEvent(0, ev0, 0);
    k_agg1<<<wb, 256>>>(h1, b1, t1);

    // Layer 2
    k_gemm_tc<64, true, false><<<gb, 256, SM2>>>(t1, W2, dinv, h2, NN);
    k_agg2<<<1184, 256>>>(h2, b2, out);
}